// round 1
// baseline (speedup 1.0000x reference)
#include <cuda_runtime.h>

// Row-wise geometry kernel: 6 points (x,y) per row ->
//   out[row][0:15]  = pairwise distances (lexicographic pairs)
//   out[row][15:35] = triplet angles at middle vertex, degrees
//   out[row][35:55] = triangle areas
//
// Strategy: compute all 15 diff vectors + rsqrt once; reuse for cosines
// (norms of v1,v2 ARE pairwise distances) and for area shoelace terms.
// Stage 128 rows x 55 outputs in SMEM, flush coalesced as float4.

#define NTH  128
#define NOUT 55
#define R2D  57.29577951308232f

__device__ __forceinline__ float acos_deg(float x) {
    // Abramowitz & Stegun 4.4.46: acos(x) = sqrt(1-x)*P7(x), |eps| <= 2e-8 rad
    float xa = fabsf(x);
    float p = fmaf(xa, -0.0012624911f, 0.0066700901f);
    p = fmaf(p, xa, -0.0170881256f);
    p = fmaf(p, xa,  0.0308918810f);
    p = fmaf(p, xa, -0.0501743046f);
    p = fmaf(p, xa,  0.0889789874f);
    p = fmaf(p, xa, -0.2145988016f);
    p = fmaf(p, xa,  1.5707963050f);
    float r = sqrtf(1.0f - xa) * p * R2D;   // acos(|x|) in degrees
    return (x >= 0.0f) ? r : (180.0f - r);
}

__global__ __launch_bounds__(NTH)
void geom55_kernel(const float2* __restrict__ a0, const float2* __restrict__ a1,
                   const float2* __restrict__ a2, const float2* __restrict__ a3,
                   const float2* __restrict__ a4, const float2* __restrict__ a5,
                   float* __restrict__ out, int n)
{
    __shared__ float s[NTH * NOUT];   // 28160 bytes

    const int tid = threadIdx.x;
    const int b   = blockIdx.x * NTH + tid;

    if (b < n) {
        float px[6], py[6];
        {
            float2 t;
            t = a0[b]; px[0] = t.x; py[0] = t.y;
            t = a1[b]; px[1] = t.x; py[1] = t.y;
            t = a2[b]; px[2] = t.x; py[2] = t.y;
            t = a3[b]; px[3] = t.x; py[3] = t.y;
            t = a4[b]; px[4] = t.x; py[4] = t.y;
            t = a5[b]; px[5] = t.x; py[5] = t.y;
        }

        const int PRI[15] = {0,0,0,0,0, 1,1,1,1, 2,2,2, 3,3, 4};
        const int PRJ[15] = {1,2,3,4,5, 2,3,4,5, 3,4,5, 4,5, 5};

        float dxv[15], dyv[15], rsq[15];
        float* srow = &s[tid * NOUT];

        #pragma unroll
        for (int q = 0; q < 15; q++) {
            float ddx = px[PRI[q]] - px[PRJ[q]];
            float ddy = py[PRI[q]] - py[PRJ[q]];
            float sq  = fmaf(ddx, ddx, ddy * ddy);
            float r   = rsqrtf(sq);
            dxv[q] = ddx; dyv[q] = ddy; rsq[q] = r;
            srow[q] = sq * r;                      // distance = sq * rsqrt(sq)
        }

        const int TI[20] = {0,0,0,0,0,0,0,0,0,0, 1,1,1,1,1,1, 2,2,2, 3};
        const int TJ[20] = {1,1,1,1,2,2,2,3,3,4, 2,2,2,3,3,4, 3,3,4, 4};
        const int TK[20] = {2,3,4,5,3,4,5,4,5,5, 3,4,5,4,5,5, 4,5,5, 5};
        const int POFF[5] = {0,5,9,12,14};         // pidx(i,j) = POFF[i]+(j-i-1)

        #pragma unroll
        for (int q = 0; q < 20; q++) {
            const int i = TI[q], j = TJ[q], k = TK[q];
            const int eij = POFF[i] + (j - i - 1);
            const int ejk = POFF[j] + (k - j - 1);
            const int eik = POFF[i] + (k - i - 1);

            // v1 = p_i - p_j = diff_ij ; v2 = p_k - p_j = -diff_jk
            float dot = fmaf(dxv[eij], dxv[ejk], dyv[eij] * dyv[ejk]);
            float c   = -dot * rsq[eij] * rsq[ejk];
            c = fminf(1.0f, fmaxf(-1.0f, c));
            srow[15 + q] = acos_deg(c);

            // shoelace: x_i*(y_j-y_k) + x_j*(y_k-y_i) + x_k*(y_i-y_j)
            //         = x_i*dy_jk - x_j*dy_ik + x_k*dy_ij
            float cr = fmaf(px[i], dyv[ejk], fmaf(px[k], dyv[eij], -px[j] * dyv[eik]));
            srow[35 + q] = 0.5f * fabsf(cr);
        }
    }
    __syncthreads();

    // Coalesced flush of this block's chunk
    const long long base = (long long)blockIdx.x * (NTH * NOUT);
    int rows = n - blockIdx.x * NTH;
    if (rows > NTH) rows = NTH;
    const int tot = rows * NOUT;

    if ((tot & 3) == 0) {
        const float4* s4 = reinterpret_cast<const float4*>(s);
        float4* o4 = reinterpret_cast<float4*>(out + base);
        const int nv = tot >> 2;   // 1760 for full block
        for (int q = tid; q < nv; q += NTH) o4[q] = s4[q];
    } else {
        for (int q = tid; q < tot; q += NTH) out[base + q] = s[q];
    }
}

extern "C" void kernel_launch(void* const* d_in, const int* in_sizes, int n_in,
                              void* d_out, int out_size) {
    const int n = in_sizes[0] / 2;          // rows (B)
    const int grid = (n + NTH - 1) / NTH;
    geom55_kernel<<<grid, NTH>>>(
        (const float2*)d_in[0], (const float2*)d_in[1],
        (const float2*)d_in[2], (const float2*)d_in[3],
        (const float2*)d_in[4], (const float2*)d_in[5],
        (float*)d_out, n);
}

// round 5
// speedup vs baseline: 1.0103x; 1.0103x over previous
#include <cuda_runtime.h>
#include <cstdint>

// Row-wise geometry kernel: 6 points (x,y) per row ->
//   out[row][0:15]  = pairwise distances (lexicographic pairs)
//   out[row][15:35] = triplet angles at middle vertex, degrees
//   out[row][35:55] = triangle areas
//
// R2: flush the 128x55 SMEM staging tile with a single cp.async.bulk (TMA)
// store instead of a per-thread STG.128 loop; evict-first (__ldcs) input loads.

#define NTH  128
#define NOUT 55
#define R2D  57.29577951308232f

__device__ __forceinline__ float acos_deg(float x) {
    // Abramowitz & Stegun 4.4.46: acos(x) = sqrt(1-x)*P7(x), |eps| <= 2e-8 rad
    float xa = fabsf(x);
    float p = fmaf(xa, -0.0012624911f, 0.0066700901f);
    p = fmaf(p, xa, -0.0170881256f);
    p = fmaf(p, xa,  0.0308918810f);
    p = fmaf(p, xa, -0.0501743046f);
    p = fmaf(p, xa,  0.0889789874f);
    p = fmaf(p, xa, -0.2145988016f);
    p = fmaf(p, xa,  1.5707963050f);
    float r = sqrtf(1.0f - xa) * p * R2D;   // acos(|x|) in degrees
    return (x >= 0.0f) ? r : (180.0f - r);
}

__global__ __launch_bounds__(NTH)
void geom55_kernel(const float2* __restrict__ a0, const float2* __restrict__ a1,
                   const float2* __restrict__ a2, const float2* __restrict__ a3,
                   const float2* __restrict__ a4, const float2* __restrict__ a5,
                   float* __restrict__ out, int n)
{
    __shared__ __align__(16) float s[NTH * NOUT];   // 28160 bytes

    const int tid = threadIdx.x;
    const int b   = blockIdx.x * NTH + tid;

    if (b < n) {
        float px[6], py[6];
        {
            float2 t;
            t = __ldcs(&a0[b]); px[0] = t.x; py[0] = t.y;
            t = __ldcs(&a1[b]); px[1] = t.x; py[1] = t.y;
            t = __ldcs(&a2[b]); px[2] = t.x; py[2] = t.y;
            t = __ldcs(&a3[b]); px[3] = t.x; py[3] = t.y;
            t = __ldcs(&a4[b]); px[4] = t.x; py[4] = t.y;
            t = __ldcs(&a5[b]); px[5] = t.x; py[5] = t.y;
        }

        const int PRI[15] = {0,0,0,0,0, 1,1,1,1, 2,2,2, 3,3, 4};
        const int PRJ[15] = {1,2,3,4,5, 2,3,4,5, 3,4,5, 4,5, 5};

        float dxv[15], dyv[15], rsq[15];
        float* srow = &s[tid * NOUT];

        #pragma unroll
        for (int q = 0; q < 15; q++) {
            float ddx = px[PRI[q]] - px[PRJ[q]];
            float ddy = py[PRI[q]] - py[PRJ[q]];
            float sq  = fmaf(ddx, ddx, ddy * ddy);
            float r   = rsqrtf(sq);
            dxv[q] = ddx; dyv[q] = ddy; rsq[q] = r;
            srow[q] = sq * r;                      // distance = sq * rsqrt(sq)
        }

        const int TI[20] = {0,0,0,0,0,0,0,0,0,0, 1,1,1,1,1,1, 2,2,2, 3};
        const int TJ[20] = {1,1,1,1,2,2,2,3,3,4, 2,2,2,3,3,4, 3,3,4, 4};
        const int TK[20] = {2,3,4,5,3,4,5,4,5,5, 3,4,5,4,5,5, 4,5,5, 5};
        const int POFF[5] = {0,5,9,12,14};         // pidx(i,j) = POFF[i]+(j-i-1)

        #pragma unroll
        for (int q = 0; q < 20; q++) {
            const int i = TI[q], j = TJ[q], k = TK[q];
            const int eij = POFF[i] + (j - i - 1);
            const int ejk = POFF[j] + (k - j - 1);
            const int eik = POFF[i] + (k - i - 1);

            // v1 = p_i - p_j = diff_ij ; v2 = p_k - p_j = -diff_jk
            float dot = fmaf(dxv[eij], dxv[ejk], dyv[eij] * dyv[ejk]);
            float c   = -dot * rsq[eij] * rsq[ejk];
            c = fminf(1.0f, fmaxf(-1.0f, c));
            srow[15 + q] = acos_deg(c);

            // shoelace: x_i*dy_jk - x_j*dy_ik + x_k*dy_ij
            float cr = fmaf(px[i], dyv[ejk], fmaf(px[k], dyv[eij], -px[j] * dyv[eik]));
            srow[35 + q] = 0.5f * fabsf(cr);
        }
    }
    __syncthreads();

    const long long base = (long long)blockIdx.x * (NTH * NOUT);
    int rows = n - blockIdx.x * NTH;
    if (rows > NTH) rows = NTH;

    if (rows == NTH) {
        // Full block: single TMA bulk store SMEM -> GMEM (28160 B, 16B-aligned)
        if (tid == 0) {
            uint32_t saddr;
            asm volatile("{ .reg .u64 t; cvta.to.shared.u64 t, %1; cvt.u32.u64 %0, t; }"
                         : "=r"(saddr) : "l"(s));
            asm volatile("fence.proxy.async.shared::cta;" ::: "memory");
            asm volatile("cp.async.bulk.global.shared::cta.bulk_group [%0], [%1], %2;"
                         :: "l"(out + base), "r"(saddr), "n"(NTH * NOUT * 4)
                         : "memory");
            asm volatile("cp.async.bulk.commit_group;" ::: "memory");
            asm volatile("cp.async.bulk.wait_group 0;" ::: "memory");
        }
    } else {
        // Partial tail block (not taken for B = 2,000,000): scalar flush
        const int tot = rows * NOUT;
        for (int q = tid; q < tot; q += NTH) out[base + q] = s[q];
    }
}

extern "C" void kernel_launch(void* const* d_in, const int* in_sizes, int n_in,
                              void* d_out, int out_size) {
    const int n = in_sizes[0] / 2;          // rows (B)
    const int grid = (n + NTH - 1) / NTH;
    geom55_kernel<<<grid, NTH>>>(
        (const float2*)d_in[0], (const float2*)d_in[1],
        (const float2*)d_in[2], (const float2*)d_in[3],
        (const float2*)d_in[4], (const float2*)d_in[5],
        (float*)d_out, n);
}